// round 15
// baseline (speedup 1.0000x reference)
#include <cuda_runtime.h>
#include <cstdint>

#define M_MOL 64
#define N_ATM 512
#define RC2 49.0f        // (cutoff + shell)^2 = 7^2
#define I_TILE 8
#define NTHREADS 256
#define ROW_FLOATS (N_ATM * 3)      // 1536 floats = 6144 bytes per output row
#define ROW_BYTES  (ROW_FLOATS * 4)

__device__ __forceinline__ uint32_t smem_u32(const void* p) {
    uint32_t a;
    asm("{ .reg .u64 t; cvta.to.shared.u64 t, %1; cvt.u32.u64 %0, t; }"
        : "=r"(a) : "l"(p));
    return a;
}

__global__ __launch_bounds__(NTHREADS) void nbl_kernel(
    const float* __restrict__ pos,   // [64, 512, 3]
    float* __restrict__ out)         // [64, 512, 512, 3]
{
    __shared__ __align__(16)  float sp[ROW_FLOATS];       // positions, 6 KB
    __shared__ __align__(128) float buf[2][ROW_FLOATS];   // row staging, 12 KB

    const int m = blockIdx.y;
    const float* pm = pos + (size_t)m * ROW_FLOATS;

    for (int t = threadIdx.x; t < ROW_FLOATS; t += NTHREADS)
        sp[t] = pm[t];
    __syncthreads();

    const int i0 = blockIdx.x * I_TILE;
    const int t  = threadIdx.x;

    #pragma unroll
    for (int ii = 0; ii < I_TILE; ii++) {
        float* rb = buf[ii & 1];

        // buffer recycle: wait until the TMA issued 2 iterations ago has
        // finished READING this buffer (<=1 group pending = ii-1's only)
        if (ii >= 2 && t == 0)
            asm volatile("cp.async.bulk.wait_group.read 1;" ::: "memory");
        __syncthreads();

        const int i = i0 + ii;
        const float xi = sp[i * 3 + 0];   // broadcast reads
        const float yi = sp[i * 3 + 1];
        const float zi = sp[i * 3 + 2];

        // compute full row into staging smem (stride-3: conflict-free)
        #pragma unroll
        for (int jb = 0; jb < N_ATM / NTHREADS; jb++) {
            const int j = jb * NTHREADS + t;
            const float dx = sp[j * 3 + 0] - xi;
            const float dy = sp[j * 3 + 1] - yi;
            const float dz = sp[j * 3 + 2] - zi;
            const float d2 = dx * dx + dy * dy + dz * dz;
            const bool keep = (d2 < RC2) && (j != i);
            rb[j * 3 + 0] = keep ? dx : 0.0f;
            rb[j * 3 + 1] = keep ? dy : 0.0f;
            rb[j * 3 + 2] = keep ? dz : 0.0f;
        }
        __syncthreads();

        // one thread pushes the whole 6 KB row via TMA bulk store
        if (t == 0) {
            asm volatile("fence.proxy.async.shared::cta;" ::: "memory");
            const float* g = out + ((size_t)(m * N_ATM + i)) * ROW_FLOATS;
            asm volatile(
                "cp.async.bulk.global.shared::cta.bulk_group [%0], [%1], %2;"
                :: "l"(g), "r"(smem_u32(rb)), "n"(ROW_BYTES) : "memory");
            asm volatile("cp.async.bulk.commit_group;" ::: "memory");
        }
    }

    // drain all outstanding bulk stores before kernel exit
    if (t == 0)
        asm volatile("cp.async.bulk.wait_group 0;" ::: "memory");
}

extern "C" void kernel_launch(void* const* d_in, const int* in_sizes, int n_in,
                              void* d_out, int out_size)
{
    const float* pos = (const float*)d_in[0];
    float* out = (float*)d_out;

    dim3 grid(N_ATM / I_TILE, M_MOL);   // (64, 64)
    nbl_kernel<<<grid, NTHREADS>>>(pos, out);
}